// round 4
// baseline (speedup 1.0000x reference)
#include <cuda_runtime.h>
#include <math.h>

// Problem constants
#define B_    16
#define CIN   512
#define T_    4096
#define E_    256
#define NC    1024
#define NTOK  (B_ * T_)          // 65536
#define NGATH 2048               // gather blocks (32 tokens each)

typedef unsigned long long ULL;

// ---------------------------------------------------------------------------
// Scratch (static __device__ arrays — no runtime allocation)
// ---------------------------------------------------------------------------
__device__ float g_x[(size_t)NTOK * E_];   // 64 MiB projected features [n][e]
__device__ ULL   g_minpack[NTOK];          // packed (dist_bits<<32 | idx)
__device__ int   g_count[NC];
__device__ float g_enorm[NC];
__device__ float g_losspart[NGATH];

// ---------------------------------------------------------------------------
// Packed fp32x2 FMA (Blackwell FFMA2 — only reachable via PTX)
// ---------------------------------------------------------------------------
__device__ __forceinline__ ULL ffma2(ULL a, ULL b, ULL c) {
    ULL d;
    asm("fma.rn.f32x2 %0, %1, %2, %3;" : "=l"(d) : "l"(a), "l"(b), "l"(c));
    return d;
}
union F4U { float4 f; ULL u[2]; };

__device__ __forceinline__ float lo32(ULL v) { return __uint_as_float((unsigned)v); }
__device__ __forceinline__ float hi32(ULL v) { return __uint_as_float((unsigned)(v >> 32)); }

// ---------------------------------------------------------------------------
// Init: minpack -> +inf, counts -> 0
// ---------------------------------------------------------------------------
__global__ void init_k() {
    int i = blockIdx.x * blockDim.x + threadIdx.x;
    if (i < NTOK) g_minpack[i] = 0xFFFFFFFFFFFFFFFFull;
    if (i < NC)   g_count[i]   = 0;
}

// ---------------------------------------------------------------------------
// Codebook row norms: one warp per row
// ---------------------------------------------------------------------------
__global__ void enorm_k(const float* __restrict__ embed) {
    int warp = (blockIdx.x * blockDim.x + threadIdx.x) >> 5;
    int lane = threadIdx.x & 31;
    if (warp >= NC) return;
    const float* row = embed + (size_t)warp * E_;
    float s = 0.f;
    #pragma unroll
    for (int e = lane; e < E_; e += 32) { float v = row[e]; s += v * v; }
    #pragma unroll
    for (int o = 16; o; o >>= 1) s += __shfl_down_sync(0xffffffffu, s, o);
    if (lane == 0) g_enorm[warp] = s;
}

// ---------------------------------------------------------------------------
// GEMM A: x[n][e] = sum_c in[b][c][t] * W[e][c] + bias[e]
// 128(t) x 128(e) tile, BK=16, 256 threads, 8x8 microtile via FFMA2,
// double-buffered smem. B (W) tile stored DUPLICATED so (b,b) pairs come
// straight from LDS.128; A pairs are naturally adjacent.
// ---------------------------------------------------------------------------
__global__ __launch_bounds__(256, 2) void gemmA_k(const float* __restrict__ A_all,
                                                  const float* __restrict__ W,
                                                  const float* __restrict__ bias) {
    __shared__ float sA[2][16][128];      // [stage][c][t]
    __shared__ float sB2[2][16][264];     // [stage][c][2e dup] (pad 264)

    const int t0 = blockIdx.x * 128;
    const int e0 = blockIdx.y * 128;
    const int b  = blockIdx.z;
    const float* A = A_all + (size_t)b * CIN * T_;

    const int tid = threadIdx.x;
    const int tx = tid & 15;              // e direction
    const int ty = tid >> 4;              // t direction

    // loader indices (fixed per thread)
    const int a_kk0 = tid >> 5,  a_t4  = tid & 31;          // l=0
    const int a_kk1 = (tid + 256) >> 5;                     // l=1 (same a_t4)
    const int w_ee  = tid >> 2,  w_cq  = tid & 3;           // l=0: ee 0..63
    // l=1: ee 64..127, same cq

    ULL acc[4][8];
    #pragma unroll
    for (int ip = 0; ip < 4; ip++)
        #pragma unroll
        for (int j = 0; j < 8; j++) acc[ip][j] = 0ull;

    float4 pa0, pa1, pw0, pw1;

    // ---- load tile 0 ----
    {
        const int c0 = 0;
        pa0 = *reinterpret_cast<const float4*>(A + (size_t)(c0 + a_kk0) * T_ + t0 + a_t4 * 4);
        pa1 = *reinterpret_cast<const float4*>(A + (size_t)(c0 + a_kk1) * T_ + t0 + a_t4 * 4);
        pw0 = *reinterpret_cast<const float4*>(W + (size_t)(e0 + w_ee) * CIN + c0 + w_cq * 4);
        pw1 = *reinterpret_cast<const float4*>(W + (size_t)(e0 + w_ee + 64) * CIN + c0 + w_cq * 4);
        *reinterpret_cast<float4*>(&sA[0][a_kk0][a_t4 * 4]) = pa0;
        *reinterpret_cast<float4*>(&sA[0][a_kk1][a_t4 * 4]) = pa1;
        *reinterpret_cast<float2*>(&sB2[0][w_cq * 4 + 0][2 * w_ee]) = make_float2(pw0.x, pw0.x);
        *reinterpret_cast<float2*>(&sB2[0][w_cq * 4 + 1][2 * w_ee]) = make_float2(pw0.y, pw0.y);
        *reinterpret_cast<float2*>(&sB2[0][w_cq * 4 + 2][2 * w_ee]) = make_float2(pw0.z, pw0.z);
        *reinterpret_cast<float2*>(&sB2[0][w_cq * 4 + 3][2 * w_ee]) = make_float2(pw0.w, pw0.w);
        *reinterpret_cast<float2*>(&sB2[0][w_cq * 4 + 0][2 * (w_ee + 64)]) = make_float2(pw1.x, pw1.x);
        *reinterpret_cast<float2*>(&sB2[0][w_cq * 4 + 1][2 * (w_ee + 64)]) = make_float2(pw1.y, pw1.y);
        *reinterpret_cast<float2*>(&sB2[0][w_cq * 4 + 2][2 * (w_ee + 64)]) = make_float2(pw1.z, pw1.z);
        *reinterpret_cast<float2*>(&sB2[0][w_cq * 4 + 3][2 * (w_ee + 64)]) = make_float2(pw1.w, pw1.w);
    }
    __syncthreads();

    const int NITER = CIN / 16;   // 32
    for (int it = 0; it < NITER; ++it) {
        const int cur = it & 1;
        const bool more = (it + 1 < NITER);
        if (more) {
            const int c0 = (it + 1) * 16;
            pa0 = *reinterpret_cast<const float4*>(A + (size_t)(c0 + a_kk0) * T_ + t0 + a_t4 * 4);
            pa1 = *reinterpret_cast<const float4*>(A + (size_t)(c0 + a_kk1) * T_ + t0 + a_t4 * 4);
            pw0 = *reinterpret_cast<const float4*>(W + (size_t)(e0 + w_ee) * CIN + c0 + w_cq * 4);
            pw1 = *reinterpret_cast<const float4*>(W + (size_t)(e0 + w_ee + 64) * CIN + c0 + w_cq * 4);
        }

        #pragma unroll
        for (int kk = 0; kk < 16; kk++) {
            F4U a0, a1;
            a0.f = *reinterpret_cast<const float4*>(&sA[cur][kk][ty * 8]);
            a1.f = *reinterpret_cast<const float4*>(&sA[cur][kk][ty * 8 + 4]);
            ULL a2[4] = { a0.u[0], a0.u[1], a1.u[0], a1.u[1] };
            F4U b0, b1, b2_, b3;
            b0.f  = *reinterpret_cast<const float4*>(&sB2[cur][kk][tx * 16 + 0]);
            b1.f  = *reinterpret_cast<const float4*>(&sB2[cur][kk][tx * 16 + 4]);
            b2_.f = *reinterpret_cast<const float4*>(&sB2[cur][kk][tx * 16 + 8]);
            b3.f  = *reinterpret_cast<const float4*>(&sB2[cur][kk][tx * 16 + 12]);
            ULL bb[8] = { b0.u[0], b0.u[1], b1.u[0], b1.u[1],
                          b2_.u[0], b2_.u[1], b3.u[0], b3.u[1] };
            #pragma unroll
            for (int ip = 0; ip < 4; ip++)
                #pragma unroll
                for (int j = 0; j < 8; j++)
                    acc[ip][j] = ffma2(a2[ip], bb[j], acc[ip][j]);
        }

        if (more) {
            const int nxt = cur ^ 1;
            *reinterpret_cast<float4*>(&sA[nxt][a_kk0][a_t4 * 4]) = pa0;
            *reinterpret_cast<float4*>(&sA[nxt][a_kk1][a_t4 * 4]) = pa1;
            *reinterpret_cast<float2*>(&sB2[nxt][w_cq * 4 + 0][2 * w_ee]) = make_float2(pw0.x, pw0.x);
            *reinterpret_cast<float2*>(&sB2[nxt][w_cq * 4 + 1][2 * w_ee]) = make_float2(pw0.y, pw0.y);
            *reinterpret_cast<float2*>(&sB2[nxt][w_cq * 4 + 2][2 * w_ee]) = make_float2(pw0.z, pw0.z);
            *reinterpret_cast<float2*>(&sB2[nxt][w_cq * 4 + 3][2 * w_ee]) = make_float2(pw0.w, pw0.w);
            *reinterpret_cast<float2*>(&sB2[nxt][w_cq * 4 + 0][2 * (w_ee + 64)]) = make_float2(pw1.x, pw1.x);
            *reinterpret_cast<float2*>(&sB2[nxt][w_cq * 4 + 1][2 * (w_ee + 64)]) = make_float2(pw1.y, pw1.y);
            *reinterpret_cast<float2*>(&sB2[nxt][w_cq * 4 + 2][2 * (w_ee + 64)]) = make_float2(pw1.z, pw1.z);
            *reinterpret_cast<float2*>(&sB2[nxt][w_cq * 4 + 3][2 * (w_ee + 64)]) = make_float2(pw1.w, pw1.w);
        }
        __syncthreads();
    }

    float bia[8];
    #pragma unroll
    for (int j = 0; j < 8; j++) bia[j] = bias[e0 + tx * 8 + j];

    #pragma unroll
    for (int ip = 0; ip < 4; ip++) {
        #pragma unroll
        for (int h = 0; h < 2; h++) {
            const int i = 2 * ip + h;
            const int n = b * T_ + t0 + ty * 8 + i;
            float v[8];
            #pragma unroll
            for (int j = 0; j < 8; j++)
                v[j] = (h ? hi32(acc[ip][j]) : lo32(acc[ip][j])) + bia[j];
            float* o = g_x + (size_t)n * E_ + e0 + tx * 8;
            *reinterpret_cast<float4*>(o)     = make_float4(v[0], v[1], v[2], v[3]);
            *reinterpret_cast<float4*>(o + 4) = make_float4(v[4], v[5], v[6], v[7]);
        }
    }
}

// ---------------------------------------------------------------------------
// GEMM B + fused argmin: s[n][k] = x[n]·embed[k];  m = ||e_k||^2 - 2 s
// Same FFMA2 + double-buffer structure. E tile duplicated.
// ---------------------------------------------------------------------------
__device__ __forceinline__ unsigned fl2ord(float f) {
    unsigned u = __float_as_uint(f);
    return (u & 0x80000000u) ? ~u : (u | 0x80000000u);
}

__global__ __launch_bounds__(256, 2) void gemmB_k(const float* __restrict__ embed) {
    __shared__ float sX[2][16][132];      // [stage][e][n] (pad 132: conflict-free scatter)
    __shared__ float sE2[2][16][264];     // [stage][e][2k dup]
    __shared__ ULL   sMin[128];

    const int n0 = blockIdx.x * 128;
    const int k0 = blockIdx.y * 128;
    const int tid = threadIdx.x;
    const int tx = tid & 15;              // k direction
    const int ty = tid >> 4;              // n direction

    if (tid < 128) sMin[tid] = 0xFFFFFFFFFFFFFFFFull;

    const int rr0 = tid >> 2, cq = tid & 3;     // l=0 row; l=1 row = rr0+64

    ULL acc[4][8];
    #pragma unroll
    for (int ip = 0; ip < 4; ip++)
        #pragma unroll
        for (int j = 0; j < 8; j++) acc[ip][j] = 0ull;

    float4 px0, px1, pe0, pe1;

    {
        const int c0 = 0;
        px0 = *reinterpret_cast<const float4*>(g_x + (size_t)(n0 + rr0) * E_ + c0 + cq * 4);
        px1 = *reinterpret_cast<const float4*>(g_x + (size_t)(n0 + rr0 + 64) * E_ + c0 + cq * 4);
        pe0 = *reinterpret_cast<const float4*>(embed + (size_t)(k0 + rr0) * E_ + c0 + cq * 4);
        pe1 = *reinterpret_cast<const float4*>(embed + (size_t)(k0 + rr0 + 64) * E_ + c0 + cq * 4);
        sX[0][cq * 4 + 0][rr0] = px0.x;  sX[0][cq * 4 + 1][rr0] = px0.y;
        sX[0][cq * 4 + 2][rr0] = px0.z;  sX[0][cq * 4 + 3][rr0] = px0.w;
        sX[0][cq * 4 + 0][rr0 + 64] = px1.x;  sX[0][cq * 4 + 1][rr0 + 64] = px1.y;
        sX[0][cq * 4 + 2][rr0 + 64] = px1.z;  sX[0][cq * 4 + 3][rr0 + 64] = px1.w;
        *reinterpret_cast<float2*>(&sE2[0][cq * 4 + 0][2 * rr0]) = make_float2(pe0.x, pe0.x);
        *reinterpret_cast<float2*>(&sE2[0][cq * 4 + 1][2 * rr0]) = make_float2(pe0.y, pe0.y);
        *reinterpret_cast<float2*>(&sE2[0][cq * 4 + 2][2 * rr0]) = make_float2(pe0.z, pe0.z);
        *reinterpret_cast<float2*>(&sE2[0][cq * 4 + 3][2 * rr0]) = make_float2(pe0.w, pe0.w);
        *reinterpret_cast<float2*>(&sE2[0][cq * 4 + 0][2 * (rr0 + 64)]) = make_float2(pe1.x, pe1.x);
        *reinterpret_cast<float2*>(&sE2[0][cq * 4 + 1][2 * (rr0 + 64)]) = make_float2(pe1.y, pe1.y);
        *reinterpret_cast<float2*>(&sE2[0][cq * 4 + 2][2 * (rr0 + 64)]) = make_float2(pe1.z, pe1.z);
        *reinterpret_cast<float2*>(&sE2[0][cq * 4 + 3][2 * (rr0 + 64)]) = make_float2(pe1.w, pe1.w);
    }
    __syncthreads();

    const int NITER = E_ / 16;   // 16
    for (int it = 0; it < NITER; ++it) {
        const int cur = it & 1;
        const bool more = (it + 1 < NITER);
        if (more) {
            const int c0 = (it + 1) * 16;
            px0 = *reinterpret_cast<const float4*>(g_x + (size_t)(n0 + rr0) * E_ + c0 + cq * 4);
            px1 = *reinterpret_cast<const float4*>(g_x + (size_t)(n0 + rr0 + 64) * E_ + c0 + cq * 4);
            pe0 = *reinterpret_cast<const float4*>(embed + (size_t)(k0 + rr0) * E_ + c0 + cq * 4);
            pe1 = *reinterpret_cast<const float4*>(embed + (size_t)(k0 + rr0 + 64) * E_ + c0 + cq * 4);
        }

        #pragma unroll
        for (int kk = 0; kk < 16; kk++) {
            F4U a0, a1;
            a0.f = *reinterpret_cast<const float4*>(&sX[cur][kk][ty * 8]);
            a1.f = *reinterpret_cast<const float4*>(&sX[cur][kk][ty * 8 + 4]);
            ULL a2[4] = { a0.u[0], a0.u[1], a1.u[0], a1.u[1] };
            F4U b0, b1, b2_, b3;
            b0.f  = *reinterpret_cast<const float4*>(&sE2[cur][kk][tx * 16 + 0]);
            b1.f  = *reinterpret_cast<const float4*>(&sE2[cur][kk][tx * 16 + 4]);
            b2_.f = *reinterpret_cast<const float4*>(&sE2[cur][kk][tx * 16 + 8]);
            b3.f  = *reinterpret_cast<const float4*>(&sE2[cur][kk][tx * 16 + 12]);
            ULL bb[8] = { b0.u[0], b0.u[1], b1.u[0], b1.u[1],
                          b2_.u[0], b2_.u[1], b3.u[0], b3.u[1] };
            #pragma unroll
            for (int ip = 0; ip < 4; ip++)
                #pragma unroll
                for (int j = 0; j < 8; j++)
                    acc[ip][j] = ffma2(a2[ip], bb[j], acc[ip][j]);
        }

        if (more) {
            const int nxt = cur ^ 1;
            sX[nxt][cq * 4 + 0][rr0] = px0.x;  sX[nxt][cq * 4 + 1][rr0] = px0.y;
            sX[nxt][cq * 4 + 2][rr0] = px0.z;  sX[nxt][cq * 4 + 3][rr0] = px0.w;
            sX[nxt][cq * 4 + 0][rr0 + 64] = px1.x;  sX[nxt][cq * 4 + 1][rr0 + 64] = px1.y;
            sX[nxt][cq * 4 + 2][rr0 + 64] = px1.z;  sX[nxt][cq * 4 + 3][rr0 + 64] = px1.w;
            *reinterpret_cast<float2*>(&sE2[nxt][cq * 4 + 0][2 * rr0]) = make_float2(pe0.x, pe0.x);
            *reinterpret_cast<float2*>(&sE2[nxt][cq * 4 + 1][2 * rr0]) = make_float2(pe0.y, pe0.y);
            *reinterpret_cast<float2*>(&sE2[nxt][cq * 4 + 2][2 * rr0]) = make_float2(pe0.z, pe0.z);
            *reinterpret_cast<float2*>(&sE2[nxt][cq * 4 + 3][2 * rr0]) = make_float2(pe0.w, pe0.w);
            *reinterpret_cast<float2*>(&sE2[nxt][cq * 4 + 0][2 * (rr0 + 64)]) = make_float2(pe1.x, pe1.x);
            *reinterpret_cast<float2*>(&sE2[nxt][cq * 4 + 1][2 * (rr0 + 64)]) = make_float2(pe1.y, pe1.y);
            *reinterpret_cast<float2*>(&sE2[nxt][cq * 4 + 2][2 * (rr0 + 64)]) = make_float2(pe1.z, pe1.z);
            *reinterpret_cast<float2*>(&sE2[nxt][cq * 4 + 3][2 * (rr0 + 64)]) = make_float2(pe1.w, pe1.w);
        }
        __syncthreads();
    }

    float en[8];
    #pragma unroll
    for (int j = 0; j < 8; j++) en[j] = g_enorm[k0 + tx * 8 + j];

    #pragma unroll
    for (int ip = 0; ip < 4; ip++) {
        #pragma unroll
        for (int h = 0; h < 2; h++) {
            const int i = 2 * ip + h;
            ULL best = 0xFFFFFFFFFFFFFFFFull;
            #pragma unroll
            for (int j = 0; j < 8; j++) {
                float dot = h ? hi32(acc[ip][j]) : lo32(acc[ip][j]);
                float m = en[j] - 2.0f * dot;
                ULL p = ((ULL)fl2ord(m) << 32) | (unsigned)(k0 + tx * 8 + j);
                best = (p < best) ? p : best;
            }
            atomicMin(&sMin[ty * 8 + i], best);
        }
    }
    __syncthreads();
    if (tid < 128) atomicMin(&g_minpack[n0 + tid], sMin[tid]);
}

// ---------------------------------------------------------------------------
// Gather + transpose write + loss partials + histogram
// ---------------------------------------------------------------------------
__global__ __launch_bounds__(256) void gather_k(const float* __restrict__ embed,
                                                float* __restrict__ out) {
    __shared__ float zq[32][257];
    __shared__ int   kidx[32];
    __shared__ float wsum[8];

    const int n0 = blockIdx.x * 32;
    const int b  = n0 >> 12;
    const int t0 = n0 & 4095;
    const int tid = threadIdx.x;

    if (tid < 32) {
        ULL mp = g_minpack[n0 + tid];
        int k = (int)(unsigned)(mp & 0xFFFFFFFFull);
        kidx[tid] = k;
        atomicAdd(&g_count[k], 1);
    }
    __syncthreads();

    float accl = 0.f;
    for (int idx = tid; idx < 32 * E_; idx += 256) {
        int t = idx >> 8, e = idx & 255;
        float v = embed[(size_t)kidx[t] * E_ + e];
        zq[t][e] = v;
        float d = v - g_x[(size_t)(n0 + t) * E_ + e];
        accl += d * d;
    }
    __syncthreads();

    for (int idx = tid; idx < 32 * E_; idx += 256) {
        int e = idx >> 5, t = idx & 31;
        out[(size_t)b * E_ * T_ + (size_t)e * T_ + t0 + t] = zq[t][e];
    }

    #pragma unroll
    for (int o = 16; o; o >>= 1) accl += __shfl_down_sync(0xffffffffu, accl, o);
    if ((tid & 31) == 0) wsum[tid >> 5] = accl;
    __syncthreads();
    if (tid == 0) {
        float s = 0.f;
        #pragma unroll
        for (int w = 0; w < 8; w++) s += wsum[w];
        g_losspart[blockIdx.x] = s;
    }
}

// ---------------------------------------------------------------------------
// Final scalars
// ---------------------------------------------------------------------------
__global__ void final_k(float* __restrict__ out, int out_size) {
    __shared__ float red[256];
    const int tid = threadIdx.x;

    float s = 0.f;
    for (int i = tid; i < NGATH; i += 256) s += g_losspart[i];
    red[tid] = s;
    __syncthreads();
    #pragma unroll
    for (int o = 128; o; o >>= 1) {
        if (tid < o) red[tid] += red[tid + o];
        __syncthreads();
    }
    float loss = red[0] * (1.25f / (float)((size_t)NTOK * E_));
    __syncthreads();

    float pl = 0.f;
    for (int k = tid; k < NC; k += 256) {
        float p = (float)g_count[k] * (1.0f / (float)NTOK);
        pl += p * logf(p + 1e-10f);
    }
    red[tid] = pl;
    __syncthreads();
    #pragma unroll
    for (int o = 128; o; o >>= 1) {
        if (tid < o) red[tid] += red[tid + o];
        __syncthreads();
    }
    float logperp = -red[0];

    if (tid == 0) {
        const float kconst = (float)(log(1024.0) * 4096.0);
        long long base = (long long)NTOK * E_;   // 16777216
        if (base < (long long)out_size) out[base] = loss;
        for (int i = 0; i < B_; i++)
            if (base + 1 + i < (long long)out_size) out[base + 1 + i] = kconst;
        if (base + 1 + B_ < (long long)out_size) out[base + 1 + B_] = logperp;
    }
}

// ---------------------------------------------------------------------------
// Launch
// ---------------------------------------------------------------------------
extern "C" void kernel_launch(void* const* d_in, const int* in_sizes, int n_in,
                              void* d_out, int out_size) {
    const float* inputs = (const float*)d_in[0];   // [16, 512, 4096]
    const float* proj_w = (const float*)d_in[1];   // [256, 512]
    const float* proj_b = (const float*)d_in[2];   // [256]
    const float* embed  = (const float*)d_in[3];   // [1024, 256]
    float* out = (float*)d_out;

    init_k<<<256, 256>>>();
    enorm_k<<<128, 256>>>(embed);

    dim3 gA(T_ / 128, E_ / 128, B_);               // 32 x 2 x 16
    gemmA_k<<<gA, 256>>>(inputs, proj_w, proj_b);

    dim3 gB(NTOK / 128, NC / 128);                 // 512 x 8
    gemmB_k<<<gB, 256>>>(embed);

    gather_k<<<NGATH, 256>>>(embed, out);
    final_k<<<1, 256>>>(out, out_size);
}

// round 9
// speedup vs baseline: 2.6486x; 2.6486x over previous
#include <cuda_runtime.h>
#include <math.h>

// Problem constants
#define B_    16
#define CIN   512
#define T_    4096
#define E_    256
#define NC    1024
#define NTOK  (B_ * T_)          // 65536
#define NGATH 2048               // gather blocks (32 tokens each)

typedef unsigned long long ULL;

// ---------------------------------------------------------------------------
// Scratch (static __device__ arrays — no runtime allocation)
// ---------------------------------------------------------------------------
__device__ float g_x[(size_t)NTOK * E_];   // 64 MiB projected features [n][e]
__device__ ULL   g_minpack[NTOK];          // packed (dist_bits<<32 | idx)
__device__ int   g_count[NC];
__device__ float g_enorm[NC];
__device__ float g_losspart[NGATH];

// ---------------------------------------------------------------------------
// Packed fp32x2 FMA (Blackwell FFMA2) + register duplication helper
// ---------------------------------------------------------------------------
__device__ __forceinline__ ULL ffma2(ULL a, ULL b, ULL c) {
    ULL d;
    asm("fma.rn.f32x2 %0, %1, %2, %3;" : "=l"(d) : "l"(a), "l"(b), "l"(c));
    return d;
}
__device__ __forceinline__ ULL dupf(float x) {
    ULL d;
    asm("mov.b64 %0, {%1, %1};" : "=l"(d) : "f"(x));
    return d;
}
union F4U { float4 f; ULL u[2]; };

__device__ __forceinline__ float lo32(ULL v) { return __uint_as_float((unsigned)v); }
__device__ __forceinline__ float hi32(ULL v) { return __uint_as_float((unsigned)(v >> 32)); }

// ---------------------------------------------------------------------------
// Init: minpack -> +inf, counts -> 0
// ---------------------------------------------------------------------------
__global__ void init_k() {
    int i = blockIdx.x * blockDim.x + threadIdx.x;
    if (i < NTOK) g_minpack[i] = 0xFFFFFFFFFFFFFFFFull;
    if (i < NC)   g_count[i]   = 0;
}

// ---------------------------------------------------------------------------
// Codebook row norms: one warp per row
// ---------------------------------------------------------------------------
__global__ void enorm_k(const float* __restrict__ embed) {
    int warp = (blockIdx.x * blockDim.x + threadIdx.x) >> 5;
    int lane = threadIdx.x & 31;
    if (warp >= NC) return;
    const float* row = embed + (size_t)warp * E_;
    float s = 0.f;
    #pragma unroll
    for (int e = lane; e < E_; e += 32) { float v = row[e]; s += v * v; }
    #pragma unroll
    for (int o = 16; o; o >>= 1) s += __shfl_down_sync(0xffffffffu, s, o);
    if (lane == 0) g_enorm[warp] = s;
}

// ---------------------------------------------------------------------------
// GEMM A: x[n][e] = sum_c in[b][c][t] * W[e][c] + bias[e]
// R3 tile structure (single-buffered, proven-good LDS pattern), FFMA2 inner:
// a-pairs natural from LDS.128, b duplicated in registers (mov.b64 {x,x}).
// ---------------------------------------------------------------------------
__global__ __launch_bounds__(256) void gemmA_k(const float* __restrict__ A_all,
                                               const float* __restrict__ W,
                                               const float* __restrict__ bias) {
    __shared__ float sA[16][128];      // [c][t]
    __shared__ float sB[16][132];      // [c][e] (padded)

    const int t0 = blockIdx.x * 128;
    const int e0 = blockIdx.y * 128;
    const int b  = blockIdx.z;
    const float* A = A_all + (size_t)b * CIN * T_;

    const int tid = threadIdx.x;
    const int tx = tid & 15;           // e direction
    const int ty = tid >> 4;           // t direction

    ULL acc[4][8];
    #pragma unroll
    for (int ip = 0; ip < 4; ip++)
        #pragma unroll
        for (int j = 0; j < 8; j++) acc[ip][j] = 0ull;

    float bia[8];
    #pragma unroll
    for (int j = 0; j < 8; j++) bia[j] = bias[e0 + tx * 8 + j];

    for (int c0 = 0; c0 < CIN; c0 += 16) {
        // Load A tile: 16 x 128 floats (coalesced along t)
        #pragma unroll
        for (int l = 0; l < 2; l++) {
            int idx = tid + l * 256;          // float4 index 0..511
            int kk = idx >> 5, t4 = idx & 31;
            float4 v = *reinterpret_cast<const float4*>(
                A + (size_t)(c0 + kk) * T_ + t0 + t4 * 4);
            *reinterpret_cast<float4*>(&sA[kk][t4 * 4]) = v;
        }
        // Load W tile transposed: read W[e][c] contiguous in c, store [c][e]
        #pragma unroll
        for (int l = 0; l < 2; l++) {
            int idx = tid + l * 256;
            int ee = idx >> 2, cq = idx & 3;
            float4 w = *reinterpret_cast<const float4*>(
                W + (size_t)(e0 + ee) * CIN + c0 + cq * 4);
            sB[cq * 4 + 0][ee] = w.x;
            sB[cq * 4 + 1][ee] = w.y;
            sB[cq * 4 + 2][ee] = w.z;
            sB[cq * 4 + 3][ee] = w.w;
        }
        __syncthreads();

        #pragma unroll
        for (int kk = 0; kk < 16; kk++) {
            F4U a0, a1;
            a0.f = *reinterpret_cast<const float4*>(&sA[kk][ty * 8]);
            a1.f = *reinterpret_cast<const float4*>(&sA[kk][ty * 8 + 4]);
            ULL a2[4] = { a0.u[0], a0.u[1], a1.u[0], a1.u[1] };
            float rb[8];
            *reinterpret_cast<float4*>(&rb[0]) = *reinterpret_cast<float4*>(&sB[kk][tx * 8]);
            *reinterpret_cast<float4*>(&rb[4]) = *reinterpret_cast<float4*>(&sB[kk][tx * 8 + 4]);
            ULL bb[8];
            #pragma unroll
            for (int j = 0; j < 8; j++) bb[j] = dupf(rb[j]);
            #pragma unroll
            for (int ip = 0; ip < 4; ip++)
                #pragma unroll
                for (int j = 0; j < 8; j++)
                    acc[ip][j] = ffma2(a2[ip], bb[j], acc[ip][j]);
        }
        __syncthreads();
    }

    #pragma unroll
    for (int ip = 0; ip < 4; ip++) {
        #pragma unroll
        for (int h = 0; h < 2; h++) {
            const int i = 2 * ip + h;
            const int n = b * T_ + t0 + ty * 8 + i;
            float v[8];
            #pragma unroll
            for (int j = 0; j < 8; j++)
                v[j] = (h ? hi32(acc[ip][j]) : lo32(acc[ip][j])) + bia[j];
            float* o = g_x + (size_t)n * E_ + e0 + tx * 8;
            *reinterpret_cast<float4*>(o)     = make_float4(v[0], v[1], v[2], v[3]);
            *reinterpret_cast<float4*>(o + 4) = make_float4(v[4], v[5], v[6], v[7]);
        }
    }
}

// ---------------------------------------------------------------------------
// GEMM B + fused argmin: s[n][k] = x[n]·embed[k];  m = ||e_k||^2 - 2 s
// R3 layout, FFMA2 inner with register-duplicated b.
// ---------------------------------------------------------------------------
__device__ __forceinline__ unsigned fl2ord(float f) {
    unsigned u = __float_as_uint(f);
    return (u & 0x80000000u) ? ~u : (u | 0x80000000u);
}

__global__ __launch_bounds__(256) void gemmB_k(const float* __restrict__ embed) {
    __shared__ float sX[16][132];      // [e][n]
    __shared__ float sE[16][132];      // [e][k]
    __shared__ ULL   sMin[128];

    const int n0 = blockIdx.x * 128;
    const int k0 = blockIdx.y * 128;
    const int tid = threadIdx.x;
    const int tx = tid & 15;           // k direction
    const int ty = tid >> 4;           // n direction

    if (tid < 128) sMin[tid] = 0xFFFFFFFFFFFFFFFFull;

    ULL acc[4][8];
    #pragma unroll
    for (int ip = 0; ip < 4; ip++)
        #pragma unroll
        for (int j = 0; j < 8; j++) acc[ip][j] = 0ull;

    for (int c0 = 0; c0 < E_; c0 += 16) {
        #pragma unroll
        for (int l = 0; l < 2; l++) {
            int idx = tid + l * 256;
            int rr = idx >> 2, cq = idx & 3;
            float4 v = *reinterpret_cast<const float4*>(
                g_x + (size_t)(n0 + rr) * E_ + c0 + cq * 4);
            sX[cq * 4 + 0][rr] = v.x;
            sX[cq * 4 + 1][rr] = v.y;
            sX[cq * 4 + 2][rr] = v.z;
            sX[cq * 4 + 3][rr] = v.w;
            float4 w = *reinterpret_cast<const float4*>(
                embed + (size_t)(k0 + rr) * E_ + c0 + cq * 4);
            sE[cq * 4 + 0][rr] = w.x;
            sE[cq * 4 + 1][rr] = w.y;
            sE[cq * 4 + 2][rr] = w.z;
            sE[cq * 4 + 3][rr] = w.w;
        }
        __syncthreads();

        #pragma unroll
        for (int kk = 0; kk < 16; kk++) {
            F4U a0, a1;
            a0.f = *reinterpret_cast<const float4*>(&sX[kk][ty * 8]);
            a1.f = *reinterpret_cast<const float4*>(&sX[kk][ty * 8 + 4]);
            ULL a2[4] = { a0.u[0], a0.u[1], a1.u[0], a1.u[1] };
            float rb[8];
            *reinterpret_cast<float4*>(&rb[0]) = *reinterpret_cast<float4*>(&sE[kk][tx * 8]);
            *reinterpret_cast<float4*>(&rb[4]) = *reinterpret_cast<float4*>(&sE[kk][tx * 8 + 4]);
            ULL bb[8];
            #pragma unroll
            for (int j = 0; j < 8; j++) bb[j] = dupf(rb[j]);
            #pragma unroll
            for (int ip = 0; ip < 4; ip++)
                #pragma unroll
                for (int j = 0; j < 8; j++)
                    acc[ip][j] = ffma2(a2[ip], bb[j], acc[ip][j]);
        }
        __syncthreads();
    }

    float en[8];
    #pragma unroll
    for (int j = 0; j < 8; j++) en[j] = g_enorm[k0 + tx * 8 + j];

    #pragma unroll
    for (int ip = 0; ip < 4; ip++) {
        #pragma unroll
        for (int h = 0; h < 2; h++) {
            const int i = 2 * ip + h;
            ULL best = 0xFFFFFFFFFFFFFFFFull;
            #pragma unroll
            for (int j = 0; j < 8; j++) {
                float dot = h ? hi32(acc[ip][j]) : lo32(acc[ip][j]);
                float m = en[j] - 2.0f * dot;
                ULL p = ((ULL)fl2ord(m) << 32) | (unsigned)(k0 + tx * 8 + j);
                best = (p < best) ? p : best;
            }
            atomicMin(&sMin[ty * 8 + i], best);
        }
    }
    __syncthreads();
    if (tid < 128) atomicMin(&g_minpack[n0 + tid], sMin[tid]);
}

// ---------------------------------------------------------------------------
// Gather + transpose write + loss partials + histogram
// ---------------------------------------------------------------------------
__global__ __launch_bounds__(256) void gather_k(const float* __restrict__ embed,
                                                float* __restrict__ out) {
    __shared__ float zq[32][257];
    __shared__ int   kidx[32];
    __shared__ float wsum[8];

    const int n0 = blockIdx.x * 32;
    const int b  = n0 >> 12;
    const int t0 = n0 & 4095;
    const int tid = threadIdx.x;

    if (tid < 32) {
        ULL mp = g_minpack[n0 + tid];
        int k = (int)(unsigned)(mp & 0xFFFFFFFFull);
        kidx[tid] = k;
        atomicAdd(&g_count[k], 1);
    }
    __syncthreads();

    float accl = 0.f;
    for (int idx = tid; idx < 32 * E_; idx += 256) {
        int t = idx >> 8, e = idx & 255;
        float v = embed[(size_t)kidx[t] * E_ + e];
        zq[t][e] = v;
        float d = v - g_x[(size_t)(n0 + t) * E_ + e];
        accl += d * d;
    }
    __syncthreads();

    for (int idx = tid; idx < 32 * E_; idx += 256) {
        int e = idx >> 5, t = idx & 31;
        out[(size_t)b * E_ * T_ + (size_t)e * T_ + t0 + t] = zq[t][e];
    }

    #pragma unroll
    for (int o = 16; o; o >>= 1) accl += __shfl_down_sync(0xffffffffu, accl, o);
    if ((tid & 31) == 0) wsum[tid >> 5] = accl;
    __syncthreads();
    if (tid == 0) {
        float s = 0.f;
        #pragma unroll
        for (int w = 0; w < 8; w++) s += wsum[w];
        g_losspart[blockIdx.x] = s;
    }
}

// ---------------------------------------------------------------------------
// Final scalars
// ---------------------------------------------------------------------------
__global__ void final_k(float* __restrict__ out, int out_size) {
    __shared__ float red[256];
    const int tid = threadIdx.x;

    float s = 0.f;
    for (int i = tid; i < NGATH; i += 256) s += g_losspart[i];
    red[tid] = s;
    __syncthreads();
    #pragma unroll
    for (int o = 128; o; o >>= 1) {
        if (tid < o) red[tid] += red[tid + o];
        __syncthreads();
    }
    float loss = red[0] * (1.25f / (float)((size_t)NTOK * E_));
    __syncthreads();

    float pl = 0.f;
    for (int k = tid; k < NC; k += 256) {
        float p = (float)g_count[k] * (1.0f / (float)NTOK);
        pl += p * logf(p + 1e-10f);
    }
    red[tid] = pl;
    __syncthreads();
    #pragma unroll
    for (int o = 128; o; o >>= 1) {
        if (tid < o) red[tid] += red[tid + o];
        __syncthreads();
    }
    float logperp = -red[0];

    if (tid == 0) {
        const float kconst = (float)(log(1024.0) * 4096.0);
        long long base = (long long)NTOK * E_;   // 16777216
        if (base < (long long)out_size) out[base] = loss;
        for (int i = 0; i < B_; i++)
            if (base + 1 + i < (long long)out_size) out[base + 1 + i] = kconst;
        if (base + 1 + B_ < (long long)out_size) out[base + 1 + B_] = logperp;
    }
}

// ---------------------------------------------------------------------------
// Launch
// ---------------------------------------------------------------------------
extern "C" void kernel_launch(void* const* d_in, const int* in_sizes, int n_in,
                              void* d_out, int out_size) {
    const float* inputs = (const float*)d_in[0];   // [16, 512, 4096]
    const float* proj_w = (const float*)d_in[1];   // [256, 512]
    const float* proj_b = (const float*)d_in[2];   // [256]
    const float* embed  = (const float*)d_in[3];   // [1024, 256]
    float* out = (float*)d_out;

    init_k<<<256, 256>>>();
    enorm_k<<<128, 256>>>(embed);

    dim3 gA(T_ / 128, E_ / 128, B_);               // 32 x 2 x 16
    gemmA_k<<<gA, 256>>>(inputs, proj_w, proj_b);

    dim3 gB(NTOK / 128, NC / 128);                 // 512 x 8
    gemmB_k<<<gB, 256>>>(embed);

    gather_k<<<NGATH, 256>>>(embed, out);
    final_k<<<1, 256>>>(out, out_size);
}

// round 14
// speedup vs baseline: 2.8692x; 1.0833x over previous
#include <cuda_runtime.h>
#include <math.h>

// Problem constants
#define B_    16
#define CIN   512
#define T_    4096
#define E_    256
#define NC    1024
#define NTOK  (B_ * T_)          // 65536
#define NGATH 2048               // gather blocks (32 tokens each)

typedef unsigned long long ULL;

// ---------------------------------------------------------------------------
// Scratch (static __device__ arrays — no runtime allocation)
// ---------------------------------------------------------------------------
__device__ float g_x[(size_t)NTOK * E_];   // 64 MiB projected features [n][e]
__device__ ULL   g_minpack[NTOK];          // packed (dist_bits<<32 | idx)
__device__ int   g_count[NC];
__device__ float g_enorm[NC];
__device__ float g_losspart[NGATH];

// ---------------------------------------------------------------------------
// Fused init + codebook row norms.
// 128 blocks x 256 threads = 32768 threads, 1024 warps (one per codebook row).
// ---------------------------------------------------------------------------
__global__ void enorm_init_k(const float* __restrict__ embed) {
    const int gid = blockIdx.x * blockDim.x + threadIdx.x;   // [0, 32768)
    g_minpack[gid]         = 0xFFFFFFFFFFFFFFFFull;
    g_minpack[gid + 32768] = 0xFFFFFFFFFFFFFFFFull;
    if (gid < NC) g_count[gid] = 0;

    const int warp = gid >> 5;            // [0, 1024)
    const int lane = gid & 31;
    const float* row = embed + (size_t)warp * E_;
    float s = 0.f;
    #pragma unroll
    for (int e = lane; e < E_; e += 32) { float v = row[e]; s += v * v; }
    #pragma unroll
    for (int o = 16; o; o >>= 1) s += __shfl_down_sync(0xffffffffu, s, o);
    if (lane == 0) g_enorm[warp] = s;
}

// ---------------------------------------------------------------------------
// GEMM A: x[n][e] = sum_c in[b][c][t] * W[e][c] + bias[e]
// Tile 128(t) x 128(e), BK=32 (R3 structure, deeper tile -> half the syncs),
// 256 threads, 8x8 microtile, scalar FFMA.
// ---------------------------------------------------------------------------
__global__ __launch_bounds__(256) void gemmA_k(const float* __restrict__ A_all,
                                               const float* __restrict__ W,
                                               const float* __restrict__ bias) {
    __shared__ float sA[32][128];      // [c][t]
    __shared__ float sB[32][132];      // [c][e] (padded)

    const int t0 = blockIdx.x * 128;
    const int e0 = blockIdx.y * 128;
    const int b  = blockIdx.z;
    const float* A = A_all + (size_t)b * CIN * T_;

    const int tid = threadIdx.x;
    const int tx = tid & 15;           // e direction
    const int ty = tid >> 4;           // t direction

    float acc[8][8];
    #pragma unroll
    for (int i = 0; i < 8; i++)
        #pragma unroll
        for (int j = 0; j < 8; j++) acc[i][j] = 0.f;

    float bia[8];
    #pragma unroll
    for (int j = 0; j < 8; j++) bia[j] = bias[e0 + tx * 8 + j];

    for (int c0 = 0; c0 < CIN; c0 += 32) {
        // Load A tile: 32 x 128 floats = 1024 float4 (coalesced along t)
        #pragma unroll
        for (int l = 0; l < 4; l++) {
            int idx = tid + l * 256;          // float4 index 0..1023
            int kk = idx >> 5, t4 = idx & 31;
            float4 v = *reinterpret_cast<const float4*>(
                A + (size_t)(c0 + kk) * T_ + t0 + t4 * 4);
            *reinterpret_cast<float4*>(&sA[kk][t4 * 4]) = v;
        }
        // Load W tile transposed: read W[e][c] contiguous in c, store [c][e]
        #pragma unroll
        for (int l = 0; l < 4; l++) {
            int idx = tid + l * 256;          // 0..1023
            int ee = idx >> 3, cq = idx & 7;  // ee 0..127, cq 0..7
            float4 w = *reinterpret_cast<const float4*>(
                W + (size_t)(e0 + ee) * CIN + c0 + cq * 4);
            sB[cq * 4 + 0][ee] = w.x;
            sB[cq * 4 + 1][ee] = w.y;
            sB[cq * 4 + 2][ee] = w.z;
            sB[cq * 4 + 3][ee] = w.w;
        }
        __syncthreads();

        #pragma unroll
        for (int kk = 0; kk < 32; kk++) {
            float ra[8], rb[8];
            *reinterpret_cast<float4*>(&ra[0]) = *reinterpret_cast<float4*>(&sA[kk][ty * 8]);
            *reinterpret_cast<float4*>(&ra[4]) = *reinterpret_cast<float4*>(&sA[kk][ty * 8 + 4]);
            *reinterpret_cast<float4*>(&rb[0]) = *reinterpret_cast<float4*>(&sB[kk][tx * 8]);
            *reinterpret_cast<float4*>(&rb[4]) = *reinterpret_cast<float4*>(&sB[kk][tx * 8 + 4]);
            #pragma unroll
            for (int i = 0; i < 8; i++)
                #pragma unroll
                for (int j = 0; j < 8; j++) acc[i][j] += ra[i] * rb[j];
        }
        __syncthreads();
    }

    #pragma unroll
    for (int i = 0; i < 8; i++) {
        int n = b * T_ + t0 + ty * 8 + i;
        float* o = g_x + (size_t)n * E_ + e0 + tx * 8;
        float4 v0 = make_float4(acc[i][0] + bia[0], acc[i][1] + bia[1],
                                acc[i][2] + bia[2], acc[i][3] + bia[3]);
        float4 v1 = make_float4(acc[i][4] + bia[4], acc[i][5] + bia[5],
                                acc[i][6] + bia[6], acc[i][7] + bia[7]);
        *reinterpret_cast<float4*>(o)     = v0;
        *reinterpret_cast<float4*>(o + 4) = v1;
    }
}

// ---------------------------------------------------------------------------
// GEMM B + fused argmin: s[n][k] = x[n]·embed[k];  m = ||e_k||^2 - 2 s
// BK=32 (8 iterations instead of 16). Packed order-preserving float bits ->
// atomicMin gives argmin with lowest-index tie-break (matches jnp.argmin).
// ---------------------------------------------------------------------------
__device__ __forceinline__ unsigned fl2ord(float f) {
    unsigned u = __float_as_uint(f);
    return (u & 0x80000000u) ? ~u : (u | 0x80000000u);
}

__global__ __launch_bounds__(256) void gemmB_k(const float* __restrict__ embed) {
    __shared__ float sX[32][132];      // [e][n]
    __shared__ float sE[32][132];      // [e][k]
    __shared__ ULL   sMin[128];

    const int n0 = blockIdx.x * 128;
    const int k0 = blockIdx.y * 128;
    const int tid = threadIdx.x;
    const int tx = tid & 15;           // k direction
    const int ty = tid >> 4;           // n direction

    if (tid < 128) sMin[tid] = 0xFFFFFFFFFFFFFFFFull;

    float acc[8][8];
    #pragma unroll
    for (int i = 0; i < 8; i++)
        #pragma unroll
        for (int j = 0; j < 8; j++) acc[i][j] = 0.f;

    for (int c0 = 0; c0 < E_; c0 += 32) {
        #pragma unroll
        for (int l = 0; l < 4; l++) {
            int idx = tid + l * 256;          // 0..1023
            int rr = idx >> 3, cq = idx & 7;  // rr 0..127, cq 0..7
            float4 v = *reinterpret_cast<const float4*>(
                g_x + (size_t)(n0 + rr) * E_ + c0 + cq * 4);
            sX[cq * 4 + 0][rr] = v.x;
            sX[cq * 4 + 1][rr] = v.y;
            sX[cq * 4 + 2][rr] = v.z;
            sX[cq * 4 + 3][rr] = v.w;
            float4 w = *reinterpret_cast<const float4*>(
                embed + (size_t)(k0 + rr) * E_ + c0 + cq * 4);
            sE[cq * 4 + 0][rr] = w.x;
            sE[cq * 4 + 1][rr] = w.y;
            sE[cq * 4 + 2][rr] = w.z;
            sE[cq * 4 + 3][rr] = w.w;
        }
        __syncthreads();

        #pragma unroll
        for (int kk = 0; kk < 32; kk++) {
            float ra[8], rb[8];
            *reinterpret_cast<float4*>(&ra[0]) = *reinterpret_cast<float4*>(&sX[kk][ty * 8]);
            *reinterpret_cast<float4*>(&ra[4]) = *reinterpret_cast<float4*>(&sX[kk][ty * 8 + 4]);
            *reinterpret_cast<float4*>(&rb[0]) = *reinterpret_cast<float4*>(&sE[kk][tx * 8]);
            *reinterpret_cast<float4*>(&rb[4]) = *reinterpret_cast<float4*>(&sE[kk][tx * 8 + 4]);
            #pragma unroll
            for (int i = 0; i < 8; i++)
                #pragma unroll
                for (int j = 0; j < 8; j++) acc[i][j] += ra[i] * rb[j];
        }
        __syncthreads();
    }

    float en[8];
    #pragma unroll
    for (int j = 0; j < 8; j++) en[j] = g_enorm[k0 + tx * 8 + j];

    #pragma unroll
    for (int i = 0; i < 8; i++) {
        ULL best = 0xFFFFFFFFFFFFFFFFull;
        #pragma unroll
        for (int j = 0; j < 8; j++) {
            float m = en[j] - 2.0f * acc[i][j];
            ULL p = ((ULL)fl2ord(m) << 32) | (unsigned)(k0 + tx * 8 + j);
            best = (p < best) ? p : best;
        }
        atomicMin(&sMin[ty * 8 + i], best);
    }
    __syncthreads();
    if (tid < 128) atomicMin(&g_minpack[n0 + tid], sMin[tid]);
}

// ---------------------------------------------------------------------------
// Gather + transpose write + loss partials + histogram
// 32 tokens per block, 256 threads. (R3 verbatim)
// ---------------------------------------------------------------------------
__global__ __launch_bounds__(256) void gather_k(const float* __restrict__ embed,
                                                float* __restrict__ out) {
    __shared__ float zq[32][257];
    __shared__ int   kidx[32];
    __shared__ float wsum[8];

    const int n0 = blockIdx.x * 32;
    const int b  = n0 >> 12;           // /4096
    const int t0 = n0 & 4095;
    const int tid = threadIdx.x;

    if (tid < 32) {
        ULL mp = g_minpack[n0 + tid];
        int k = (int)(unsigned)(mp & 0xFFFFFFFFull);
        kidx[tid] = k;
        atomicAdd(&g_count[k], 1);
    }
    __syncthreads();

    float accl = 0.f;
    for (int idx = tid; idx < 32 * E_; idx += 256) {
        int t = idx >> 8, e = idx & 255;
        float v = embed[(size_t)kidx[t] * E_ + e];
        zq[t][e] = v;
        float d = v - g_x[(size_t)(n0 + t) * E_ + e];
        accl += d * d;
    }
    __syncthreads();

    // transpose write: out[b][e][t], coalesced along t
    for (int idx = tid; idx < 32 * E_; idx += 256) {
        int e = idx >> 5, t = idx & 31;
        out[(size_t)b * E_ * T_ + (size_t)e * T_ + t0 + t] = zq[t][e];
    }

    #pragma unroll
    for (int o = 16; o; o >>= 1) accl += __shfl_down_sync(0xffffffffu, accl, o);
    if ((tid & 31) == 0) wsum[tid >> 5] = accl;
    __syncthreads();
    if (tid == 0) {
        float s = 0.f;
        #pragma unroll
        for (int w = 0; w < 8; w++) s += wsum[w];
        g_losspart[blockIdx.x] = s;
    }
}

// ---------------------------------------------------------------------------
// Final scalars: loss, kldiv (constant), log-perplexity (R3 verbatim)
// ---------------------------------------------------------------------------
__global__ void final_k(float* __restrict__ out, int out_size) {
    __shared__ float red[256];
    const int tid = threadIdx.x;

    float s = 0.f;
    for (int i = tid; i < NGATH; i += 256) s += g_losspart[i];
    red[tid] = s;
    __syncthreads();
    #pragma unroll
    for (int o = 128; o; o >>= 1) {
        if (tid < o) red[tid] += red[tid + o];
        __syncthreads();
    }
    float loss = red[0] * (1.25f / (float)((size_t)NTOK * E_));
    __syncthreads();

    float pl = 0.f;
    for (int k = tid; k < NC; k += 256) {
        float p = (float)g_count[k] * (1.0f / (float)NTOK);
        pl += p * logf(p + 1e-10f);
    }
    red[tid] = pl;
    __syncthreads();
    #pragma unroll
    for (int o = 128; o; o >>= 1) {
        if (tid < o) red[tid] += red[tid + o];
        __syncthreads();
    }
    float logperp = -red[0];

    if (tid == 0) {
        const float kconst = (float)(log(1024.0) * 4096.0);
        long long base = (long long)NTOK * E_;   // 16777216
        if (base < (long long)out_size) out[base] = loss;
        for (int i = 0; i < B_; i++)
            if (base + 1 + i < (long long)out_size) out[base + 1 + i] = kconst;
        if (base + 1 + B_ < (long long)out_size) out[base + 1 + B_] = logperp;
    }
}

// ---------------------------------------------------------------------------
// Launch
// ---------------------------------------------------------------------------
extern "C" void kernel_launch(void* const* d_in, const int* in_sizes, int n_in,
                              void* d_out, int out_size) {
    const float* inputs = (const float*)d_in[0];   // [16, 512, 4096]
    const float* proj_w = (const float*)d_in[1];   // [256, 512]
    const float* proj_b = (const float*)d_in[2];   // [256]
    const float* embed  = (const float*)d_in[3];   // [1024, 256]
    float* out = (float*)d_out;

    enorm_init_k<<<128, 256>>>(embed);

    dim3 gA(T_ / 128, E_ / 128, B_);               // 32 x 2 x 16
    gemmA_k<<<gA, 256>>>(inputs, proj_w, proj_b);

    dim3 gB(NTOK / 128, NC / 128);                 // 512 x 8
    gemmB_k<<<gB, 256>>>(embed);

    gather_k<<<NGATH, 256>>>(embed, out);
    final_k<<<1, 256>>>(out, out_size);
}

// round 16
// speedup vs baseline: 4.1994x; 1.4636x over previous
#include <cuda_runtime.h>
#include <cuda_bf16.h>
#include <math.h>

// Problem constants
#define B_    16
#define CIN   512
#define T_    4096
#define E_    256
#define NC    1024
#define NTOK  (B_ * T_)          // 65536
#define NGATH 2048               // gather blocks (32 tokens each)

typedef unsigned long long ULL;
typedef unsigned int       U32;

// ---------------------------------------------------------------------------
// Scratch (static __device__ arrays — no runtime allocation)
// ---------------------------------------------------------------------------
__device__ float g_x[(size_t)NTOK * E_];        // 64 MiB fp32 features [n][e]
__device__ U32   g_xb[(size_t)NTOK * 128];      // 32 MiB bf16x2 features [n][e/2]
__device__ U32   g_eb[(size_t)NC * 128];        // bf16x2 codebook [k][e/2]
__device__ U32   g_cand[(size_t)NTOK * 32];     // 32 coarse candidates per token
__device__ int   g_count[NC];
__device__ float g_enorm[NC];
__device__ float g_losspart[NGATH];

// ---------------------------------------------------------------------------
// Baseline-PTX tensor op (sm_80+, compiles under compute_103 — NOT tcgen05)
// ---------------------------------------------------------------------------
__device__ __forceinline__ void mma_bf16(float c[4], const U32 a[4], U32 b0, U32 b1) {
    asm volatile(
        "mma.sync.aligned.m16n8k16.row.col.f32.bf16.bf16.f32 "
        "{%0,%1,%2,%3}, {%4,%5,%6,%7}, {%8,%9}, {%0,%1,%2,%3};"
        : "+f"(c[0]), "+f"(c[1]), "+f"(c[2]), "+f"(c[3])
        : "r"(a[0]), "r"(a[1]), "r"(a[2]), "r"(a[3]), "r"(b0), "r"(b1));
}

__device__ __forceinline__ void top4_ins(float m, U32 kk, float d[4], U32 k[4]) {
    if (m < d[3]) {
        if (m < d[1]) {
            if (m < d[0]) {
                d[3]=d[2]; k[3]=k[2]; d[2]=d[1]; k[2]=k[1];
                d[1]=d[0]; k[1]=k[0]; d[0]=m; k[0]=kk;
            } else {
                d[3]=d[2]; k[3]=k[2]; d[2]=d[1]; k[2]=k[1];
                d[1]=m; k[1]=kk;
            }
        } else {
            if (m < d[2]) { d[3]=d[2]; k[3]=k[2]; d[2]=m; k[2]=kk; }
            else          { d[3]=m; k[3]=kk; }
        }
    }
}

// ---------------------------------------------------------------------------
// Fused init: counts, codebook norms, bf16 codebook
// ---------------------------------------------------------------------------
__global__ void enorm_init_k(const float* __restrict__ embed) {
    const int gid = blockIdx.x * blockDim.x + threadIdx.x;   // [0, 32768)
    if (gid < NC) g_count[gid] = 0;

    const int row  = gid >> 5;            // [0, 1024)
    const int lane = gid & 31;
    const float2* r2 = reinterpret_cast<const float2*>(embed + (size_t)row * E_);
    float s = 0.f;
    #pragma unroll
    for (int c2 = lane; c2 < 128; c2 += 32) {
        float2 f = r2[c2];
        s += f.x * f.x + f.y * f.y;
        __nv_bfloat162 h = __floats2bfloat162_rn(f.x, f.y);
        g_eb[(size_t)row * 128 + c2] = *reinterpret_cast<U32*>(&h);
    }
    #pragma unroll
    for (int o = 16; o; o >>= 1) s += __shfl_down_sync(0xffffffffu, s, o);
    if (lane == 0) g_enorm[row] = s;
}

// ---------------------------------------------------------------------------
// GEMM A (R14-proven) + bf16 emission in epilogue
// ---------------------------------------------------------------------------
__global__ __launch_bounds__(256) void gemmA_k(const float* __restrict__ A_all,
                                               const float* __restrict__ W,
                                               const float* __restrict__ bias) {
    __shared__ float sA[32][128];
    __shared__ float sB[32][132];

    const int t0 = blockIdx.x * 128;
    const int e0 = blockIdx.y * 128;
    const int b  = blockIdx.z;
    const float* A = A_all + (size_t)b * CIN * T_;

    const int tid = threadIdx.x;
    const int tx = tid & 15;
    const int ty = tid >> 4;

    float acc[8][8];
    #pragma unroll
    for (int i = 0; i < 8; i++)
        #pragma unroll
        for (int j = 0; j < 8; j++) acc[i][j] = 0.f;

    float bia[8];
    #pragma unroll
    for (int j = 0; j < 8; j++) bia[j] = bias[e0 + tx * 8 + j];

    for (int c0 = 0; c0 < CIN; c0 += 32) {
        #pragma unroll
        for (int l = 0; l < 4; l++) {
            int idx = tid + l * 256;
            int kk = idx >> 5, t4 = idx & 31;
            float4 v = *reinterpret_cast<const float4*>(
                A + (size_t)(c0 + kk) * T_ + t0 + t4 * 4);
            *reinterpret_cast<float4*>(&sA[kk][t4 * 4]) = v;
        }
        #pragma unroll
        for (int l = 0; l < 4; l++) {
            int idx = tid + l * 256;
            int ee = idx >> 3, cq = idx & 7;
            float4 w = *reinterpret_cast<const float4*>(
                W + (size_t)(e0 + ee) * CIN + c0 + cq * 4);
            sB[cq * 4 + 0][ee] = w.x;
            sB[cq * 4 + 1][ee] = w.y;
            sB[cq * 4 + 2][ee] = w.z;
            sB[cq * 4 + 3][ee] = w.w;
        }
        __syncthreads();

        #pragma unroll
        for (int kk = 0; kk < 32; kk++) {
            float ra[8], rb[8];
            *reinterpret_cast<float4*>(&ra[0]) = *reinterpret_cast<float4*>(&sA[kk][ty * 8]);
            *reinterpret_cast<float4*>(&ra[4]) = *reinterpret_cast<float4*>(&sA[kk][ty * 8 + 4]);
            *reinterpret_cast<float4*>(&rb[0]) = *reinterpret_cast<float4*>(&sB[kk][tx * 8]);
            *reinterpret_cast<float4*>(&rb[4]) = *reinterpret_cast<float4*>(&sB[kk][tx * 8 + 4]);
            #pragma unroll
            for (int i = 0; i < 8; i++)
                #pragma unroll
                for (int j = 0; j < 8; j++) acc[i][j] += ra[i] * rb[j];
        }
        __syncthreads();
    }

    #pragma unroll
    for (int i = 0; i < 8; i++) {
        int n = b * T_ + t0 + ty * 8 + i;
        float v[8];
        #pragma unroll
        for (int j = 0; j < 8; j++) v[j] = acc[i][j] + bia[j];
        float* o = g_x + (size_t)n * E_ + e0 + tx * 8;
        *reinterpret_cast<float4*>(o)     = make_float4(v[0], v[1], v[2], v[3]);
        *reinterpret_cast<float4*>(o + 4) = make_float4(v[4], v[5], v[6], v[7]);
        U32 pk[4];
        #pragma unroll
        for (int q = 0; q < 4; q++) {
            __nv_bfloat162 h = __floats2bfloat162_rn(v[2 * q], v[2 * q + 1]);
            pk[q] = *reinterpret_cast<U32*>(&h);
        }
        *reinterpret_cast<uint4*>(&g_xb[(size_t)n * 128 + (e0 + tx * 8) / 2]) =
            make_uint4(pk[0], pk[1], pk[2], pk[3]);
    }
}

// ---------------------------------------------------------------------------
// Coarse distance sweep via HMMA (mma.sync bf16) + per-lane running top-4.
// CTA: 128 tokens x 1024 codes, K=256. 8 warps in 4(m) x 2(n) grid; each warp
// owns 32 rows x 32 cols per 64-code tile. Dynamic smem: XS 128x132 u32
// (bf16x2, padded -> conflict-free fragment loads) + BS 64x132 + sEn.
// Per token: 2 warps x 4 lanes x top4 = 32 candidates (no merge needed).
// ---------------------------------------------------------------------------
#define XS_N   (128 * 132)
#define BS_N   (64 * 132)
#define SMEMB  ((XS_N + BS_N) * 4 + 256)

extern __shared__ U32 dynsm[];

__global__ __launch_bounds__(256) void gemmBc_k() {
    U32*   XS  = dynsm;                 // [128][132] bf16x2
    U32*   BS  = dynsm + XS_N;          // [64][132]  bf16x2
    float* sEn = (float*)(dynsm + XS_N + BS_N);   // [64]

    const int tid = threadIdx.x;
    const int w   = tid >> 5;
    const int l   = tid & 31;
    const int g   = l >> 2;            // 0..7
    const int q   = l & 3;             // 0..3
    const int wm  = w & 3;             // row group: rows wm*32..+31
    const int wn  = w >> 2;            // col group: cols wn*32..+31
    const int n0  = blockIdx.x * 128;

    // ---- load X tile (coalesced, 16B stores, stride keeps 16B alignment) ----
    const U32* xsrc = g_xb + (size_t)n0 * 128;
    #pragma unroll
    for (int c = 0; c < 16; c++) {
        int chunk = tid + c * 256;           // 0..4095
        int row = chunk >> 5, c4 = chunk & 31;
        uint4 v = *reinterpret_cast<const uint4*>(xsrc + (size_t)row * 128 + c4 * 4);
        *reinterpret_cast<uint4*>(XS + row * 132 + c4 * 4) = v;
    }

    float d4[4][4];
    U32   k4[4][4];
    #pragma unroll
    for (int s = 0; s < 4; s++)
        #pragma unroll
        for (int i = 0; i < 4; i++) { d4[s][i] = 3.0e38f; k4[s][i] = 0x7fffffffu; }

    for (int tile = 0; tile < 16; tile++) {
        const int k0 = tile * 64;
        __syncthreads();    // guards XS writes (tile 0) / BS reuse (tile>0)
        #pragma unroll
        for (int c = 0; c < 8; c++) {
            int chunk = tid + c * 256;       // 0..2047
            int row = chunk >> 5, c4 = chunk & 31;
            uint4 v = *reinterpret_cast<const uint4*>(
                g_eb + (size_t)(k0 + row) * 128 + c4 * 4);
            *reinterpret_cast<uint4*>(BS + row * 132 + c4 * 4) = v;
        }
        if (tid < 64) sEn[tid] = g_enorm[k0 + tid];
        __syncthreads();

        float acc[2][4][4];
        #pragma unroll
        for (int mf = 0; mf < 2; mf++)
            #pragma unroll
            for (int nf = 0; nf < 4; nf++)
                #pragma unroll
                for (int i = 0; i < 4; i++) acc[mf][nf][i] = 0.f;

        #pragma unroll
        for (int ks = 0; ks < 16; ks++) {
            const int kb = ks * 8 + q;       // u32 column in padded row
            U32 a[2][4];
            #pragma unroll
            for (int mf = 0; mf < 2; mf++) {
                const int rb = (wm * 32 + mf * 16) * 132 + kb;
                a[mf][0] = XS[rb + g * 132];
                a[mf][1] = XS[rb + (g + 8) * 132];
                a[mf][2] = XS[rb + g * 132 + 4];
                a[mf][3] = XS[rb + (g + 8) * 132 + 4];
            }
            #pragma unroll
            for (int nf = 0; nf < 4; nf++) {
                const int nb = (wn * 32 + nf * 8 + g) * 132 + kb;
                U32 b0 = BS[nb];
                U32 b1 = BS[nb + 4];
                #pragma unroll
                for (int mf = 0; mf < 2; mf++)
                    mma_bf16(acc[mf][nf], a[mf], b0, b1);
            }
        }

        // top-4 update: c0/c1 -> row g; c2/c3 -> row g+8 (struct mf*2 / mf*2+1)
        #pragma unroll
        for (int nf = 0; nf < 4; nf++) {
            const int nl = wn * 32 + nf * 8 + q * 2;
            const float en0 = sEn[nl], en1 = sEn[nl + 1];
            const U32 kk0 = (U32)(k0 + nl), kk1 = kk0 + 1;
            #pragma unroll
            for (int mf = 0; mf < 2; mf++) {
                top4_ins(en0 - 2.0f * acc[mf][nf][0], kk0, d4[mf*2],   k4[mf*2]);
                top4_ins(en1 - 2.0f * acc[mf][nf][1], kk1, d4[mf*2],   k4[mf*2]);
                top4_ins(en0 - 2.0f * acc[mf][nf][2], kk0, d4[mf*2+1], k4[mf*2+1]);
                top4_ins(en1 - 2.0f * acc[mf][nf][3], kk1, d4[mf*2+1], k4[mf*2+1]);
            }
        }
    }

    // write candidates: struct s=(mf,hf) covers token row wm*32+mf*16+hf*8+g
    #pragma unroll
    for (int mf = 0; mf < 2; mf++)
        #pragma unroll
        for (int hf = 0; hf < 2; hf++) {
            const int tok = n0 + wm * 32 + mf * 16 + hf * 8 + g;
            const int s = mf * 2 + hf;
            *reinterpret_cast<uint4*>(&g_cand[(size_t)tok * 32 + wn * 16 + q * 4]) =
                make_uint4(k4[s][0], k4[s][1], k4[s][2], k4[s][3]);
        }
}

// ---------------------------------------------------------------------------
// Gather: exact fp32 rescore of 32 candidates + gather + loss + histogram.
// Warp w rescores tokens 4w..4w+3; x row cached in registers across cands.
// ---------------------------------------------------------------------------
__global__ __launch_bounds__(256) void gather_k(const float* __restrict__ embed,
                                                float* __restrict__ out) {
    __shared__ float zq[32][257];
    __shared__ int   kidx[32];
    __shared__ float wsum[8];

    const int n0 = blockIdx.x * 32;
    const int b  = n0 >> 12;
    const int t0 = n0 & 4095;
    const int tid  = threadIdx.x;
    const int wid  = tid >> 5;
    const int lane = tid & 31;

    #pragma unroll
    for (int c = 0; c < 4; c++) {
        const int t = wid * 4 + c;
        const int n = n0 + t;
        const float* xr = g_x + (size_t)n * E_;
        float xv[8];
        #pragma unroll
        for (int i = 0; i < 8; i++) xv[i] = xr[lane + i * 32];

        const U32* cd = g_cand + (size_t)n * 32;
        float best_d = 3.0e38f; int best_k = 0x7fffffff;
        #pragma unroll 4
        for (int j = 0; j < 32; j++) {
            int k = (int)cd[j];
            const float* er = embed + (size_t)k * E_;
            float dot = 0.f;
            #pragma unroll
            for (int i = 0; i < 8; i++) dot += xv[i] * er[lane + i * 32];
            #pragma unroll
            for (int o = 16; o; o >>= 1) dot += __shfl_xor_sync(0xffffffffu, dot, o);
            float d = g_enorm[k] - 2.0f * dot;
            if (d < best_d || (d == best_d && k < best_k)) { best_d = d; best_k = k; }
        }
        if (lane == 0) {
            kidx[t] = best_k;
            atomicAdd(&g_count[best_k], 1);
        }
    }
    __syncthreads();

    float accl = 0.f;
    for (int idx = tid; idx < 32 * E_; idx += 256) {
        int t = idx >> 8, e = idx & 255;
        float v = embed[(size_t)kidx[t] * E_ + e];
        zq[t][e] = v;
        float d = v - g_x[(size_t)(n0 + t) * E_ + e];
        accl += d * d;
    }
    __syncthreads();

    for (int idx = tid; idx < 32 * E_; idx += 256) {
        int e = idx >> 5, t = idx & 31;
        out[(size_t)b * E_ * T_ + (size_t)e * T_ + t0 + t] = zq[t][e];
    }

    #pragma unroll
    for (int o = 16; o; o >>= 1) accl += __shfl_down_sync(0xffffffffu, accl, o);
    if ((tid & 31) == 0) wsum[tid >> 5] = accl;
    __syncthreads();
    if (tid == 0) {
        float s = 0.f;
        #pragma unroll
        for (int w = 0; w < 8; w++) s += wsum[w];
        g_losspart[blockIdx.x] = s;
    }
}

// ---------------------------------------------------------------------------
// Final scalars
// ---------------------------------------------------------------------------
__global__ void final_k(float* __restrict__ out, int out_size) {
    __shared__ float red[256];
    const int tid = threadIdx.x;

    float s = 0.f;
    for (int i = tid; i < NGATH; i += 256) s += g_losspart[i];
    red[tid] = s;
    __syncthreads();
    #pragma unroll
    for (int o = 128; o; o >>= 1) {
        if (tid < o) red[tid] += red[tid + o];
        __syncthreads();
    }
    float loss = red[0] * (1.25f / (float)((size_t)NTOK * E_));
    __syncthreads();

    float pl = 0.f;
    for (int k = tid; k < NC; k += 256) {
        float p = (float)g_count[k] * (1.0f / (float)NTOK);
        pl += p * logf(p + 1e-10f);
    }
    red[tid] = pl;
    __syncthreads();
    #pragma unroll
    for (int o = 128; o; o >>= 1) {
        if (tid < o) red[tid] += red[tid + o];
        __syncthreads();
    }
    float logperp = -red[0];

    if (tid == 0) {
        const float kconst = (float)(log(1024.0) * 4096.0);
        long long base = (long long)NTOK * E_;   // 16777216
        if (base < (long long)out_size) out[base] = loss;
        for (int i = 0; i < B_; i++)
            if (base + 1 + i < (long long)out_size) out[base + 1 + i] = kconst;
        if (base + 1 + B_ < (long long)out_size) out[base + 1 + B_] = logperp;
    }
}

// ---------------------------------------------------------------------------
// Launch
// ---------------------------------------------------------------------------
extern "C" void kernel_launch(void* const* d_in, const int* in_sizes, int n_in,
                              void* d_out, int out_size) {
    const float* inputs = (const float*)d_in[0];   // [16, 512, 4096]
    const float* proj_w = (const float*)d_in[1];   // [256, 512]
    const float* proj_b = (const float*)d_in[2];   // [256]
    const float* embed  = (const float*)d_in[3];   // [1024, 256]
    float* out = (float*)d_out;

    // Idempotent attribute set (not a stream op; persists from the first,
    // uncaptured correctness call).
    cudaFuncSetAttribute(gemmBc_k, cudaFuncAttributeMaxDynamicSharedMemorySize,
                         SMEMB);

    enorm_init_k<<<128, 256>>>(embed);

    dim3 gA(T_ / 128, E_ / 128, B_);               // 32 x 2 x 16
    gemmA_k<<<gA, 256>>>(inputs, proj_w, proj_b);

    gemmBc_k<<<NTOK / 128, 256, SMEMB>>>();        // 512 CTAs

    gather_k<<<NGATH, 256>>>(embed, out);
    final_k<<<1, 256>>>(out, out_size);
}